// round 6
// baseline (speedup 1.0000x reference)
#include <cuda_runtime.h>
#include <cuda_bf16.h>
#include <cstdint>

#define N1MAX 15000
#define N2MAX 60000

// ---------------- device scratch (static, no allocs) -------------------------
// split planes: per row [hi(CI) | lo(CI)] bf16, row pitch 4*CI bytes
__device__ __nv_bfloat16 g_f1sp[(size_t)N1MAX * 256];        // feats1 split
__device__ __nv_bfloat16 g_xsp [(size_t)N2MAX * 256];        // concat input split
__device__ __nv_bfloat16 g_hsp [(size_t)N2MAX * 128];        // conv1 output split
__device__ float g_pre [N2MAX * 64];                          // pre-BN buffer
__device__ float g_msg [27u * N2MAX * 64];                    // per-entry MMA outputs
__device__ int   g_ent  [27 * N2MAX];
__device__ int   g_entup[ 8 * N2MAX];
__device__ int   g_pos  [27 * N2MAX];
__device__ int   g_posup[N2MAX];
__device__ int   g_cnt  [27];
__device__ int   g_cntup[8];
// weight images row-interleaved: [t][o][hi(CI)|lo(CI)] bf16
__device__ __nv_bfloat16 g_Bup[8  * 64 * 256];
__device__ __nv_bfloat16 g_B1 [27 * 64 * 256];
__device__ __nv_bfloat16 g_B2 [27 * 64 * 128];
__device__ float g_part[256 * 64 * 2];
// exact tile lists
__device__ int g_tileT [13312];
__device__ int g_tileB [13312];
__device__ int g_tileTu[4096];
__device__ int g_tileBu[4096];
__device__ int g_ntiles;
__device__ int g_ntilesu;

// ---------------- helpers -----------------------------------------------------
__device__ __forceinline__ uint32_t smem_u32(const void* p) {
    uint32_t a;
    asm("{ .reg .u64 t; cvta.to.shared.u64 t, %1; cvt.u32.u64 %0, t; }"
        : "=r"(a) : "l"(p));
    return a;
}
__device__ __forceinline__ void cp16(uint32_t dst, const void* src) {
    asm volatile("cp.async.cg.shared.global [%0], [%1], 16;" :: "r"(dst), "l"(src));
}
#define CP_COMMIT() asm volatile("cp.async.commit_group;" ::: "memory")
#define CP_WAIT0()  asm volatile("cp.async.wait_group 0;" ::: "memory")

__device__ __forceinline__ void mma16816(float& c0, float& c1, float& c2, float& c3,
                                         uint32_t a0, uint32_t a1, uint32_t a2, uint32_t a3,
                                         uint32_t b0, uint32_t b1)
{
    asm volatile("mma.sync.aligned.m16n8k16.row.col.f32.bf16.bf16.f32 "
                 "{%0,%1,%2,%3}, {%4,%5,%6,%7}, {%8,%9}, {%0,%1,%2,%3};"
                 : "+f"(c0), "+f"(c1), "+f"(c2), "+f"(c3)
                 : "r"(a0), "r"(a1), "r"(a2), "r"(a3), "r"(b0), "r"(b1));
}

// ---------------- prep: counters, input/weight bf16 hi-lo splits -------------
__device__ __forceinline__ void split_write(__nv_bfloat16* hi, __nv_bfloat16* lo, float v) {
    __nv_bfloat16 h = __float2bfloat16(v);
    *hi = h;
    *lo = __float2bfloat16(v - __bfloat162float(h));
}

__global__ void prep_kernel(const float* __restrict__ feats1,
                            const float* __restrict__ feats2,
                            const float* __restrict__ wup,
                            const float* __restrict__ w1,
                            const float* __restrict__ w2,
                            int n1, int n2)
{
    const int T0 = 35;
    const int T1 = n2 * 64;
    const int T2 = n1 * 128;
    const int T3 = 8  * 128 * 64;
    const int T4 = 27 * 128 * 64;
    const int T5 = 27 * 64  * 64;
    const int total = T0 + T1 + T2 + T3 + T4 + T5;
    for (int idx = blockIdx.x * blockDim.x + threadIdx.x; idx < total;
         idx += gridDim.x * blockDim.x) {
        if (idx < T0) {
            if (idx < 27) g_cnt[idx] = 0; else g_cntup[idx - 27] = 0;
        } else if (idx < T0 + T1) {
            int j = idx - T0;
            int r = j >> 6, k = j & 63;
            split_write(&g_xsp[(size_t)r * 256 + 64 + k],
                        &g_xsp[(size_t)r * 256 + 192 + k], feats2[j]);
        } else if (idx < T0 + T1 + T2) {
            int j = idx - T0 - T1;
            int m = j >> 7, k = j & 127;
            split_write(&g_f1sp[(size_t)m * 256 + k],
                        &g_f1sp[(size_t)m * 256 + 128 + k], feats1[j]);
        } else if (idx < T0 + T1 + T2 + T3) {
            int j = idx - T0 - T1 - T2;
            int t = j >> 13, r = j & 8191;           // CI=128: per-tap 128*64
            int k = r >> 6, o = r & 63;
            __nv_bfloat16* b = g_Bup + (size_t)t * 16384 + o * 256;
            split_write(b + k, b + 128 + k, wup[j]);
        } else if (idx < T0 + T1 + T2 + T3 + T4) {
            int j = idx - T0 - T1 - T2 - T3;
            int t = j >> 13, r = j & 8191;
            int k = r >> 6, o = r & 63;
            __nv_bfloat16* b = g_B1 + (size_t)t * 16384 + o * 256;
            split_write(b + k, b + 128 + k, w1[j]);
        } else {
            int j = idx - T0 - T1 - T2 - T3 - T4;
            int t = j >> 12, r = j & 4095;           // CI=64: per-tap 64*64
            int k = r >> 6, o = r & 63;
            __nv_bfloat16* b = g_B2 + (size_t)t * 8192 + o * 128;
            split_write(b + k, b + 64 + k, w2[j]);
        }
    }
}

// ---------------- compaction fill kernels ------------------------------------
__global__ void fill_up_kernel(const int* __restrict__ up_src,
                               const int* __restrict__ up_kidx, int n2)
{
    __shared__ int sc[8], sb[8];
    int tid = threadIdx.x;
    int i = blockIdx.x * 256 + tid;
    if (tid < 8) sc[tid] = 0;
    __syncthreads();
    int t = 0, p = 0, s = 0;
    bool v = (i < n2);
    if (v) { t = up_kidx[i]; s = up_src[i]; p = atomicAdd(&sc[t], 1); }
    __syncthreads();
    if (tid < 8 && sc[tid] > 0) sb[tid] = atomicAdd(&g_cntup[tid], sc[tid]);
    __syncthreads();
    if (v) {
        int q = sb[t] + p;
        g_entup[t * n2 + q] = s;
        g_posup[i] = t * n2 + q;
    }
}

__global__ void fill_nbr_kernel(const int* __restrict__ nbr_src, int n2)
{
    __shared__ int sc[27], sb[27];
    int tid = threadIdx.x;
    int j = blockIdx.x * 256 + tid;
    if (tid < 27) sc[tid] = 0;
    __syncthreads();
    int t = 0, p = 0, s = 0;
    bool inr = (j < 27 * n2), hit = false;
    if (inr) {
        t = j / n2;
        s = nbr_src[j];
        hit = (s != n2);
        if (hit) p = atomicAdd(&sc[t], 1);
    }
    __syncthreads();
    if (tid < 27 && sc[tid] > 0) sb[tid] = atomicAdd(&g_cnt[tid], sc[tid]);
    __syncthreads();
    if (inr) {
        if (hit) {
            int q = sb[t] + p;
            g_ent[t * n2 + q] = s;
            g_pos[j] = t * n2 + q;
        } else g_pos[j] = -1;
    }
}

// ---------------- exact tile lists (one warp) --------------------------------
__global__ void build_tiles_kernel()
{
    int lane = threadIdx.x;
    unsigned full = 0xFFFFFFFFu;
    int c = (lane < 27) ? (g_cnt[lane] + 127) >> 7 : 0;
    int pre = c;
    #pragma unroll
    for (int d = 1; d < 32; d <<= 1) {
        int v = __shfl_up_sync(full, pre, d);
        if (lane >= d) pre += v;
    }
    int off = pre - c;
    for (int j = 0; j < c; ++j) { g_tileT[off + j] = lane; g_tileB[off + j] = j << 7; }
    if (lane == 31) g_ntiles = pre;

    int cu = (lane < 8) ? (g_cntup[lane] + 127) >> 7 : 0;
    int pu = cu;
    #pragma unroll
    for (int d = 1; d < 32; d <<= 1) {
        int v = __shfl_up_sync(full, pu, d);
        if (lane >= d) pu += v;
    }
    int offu = pu - cu;
    for (int j = 0; j < cu; ++j) { g_tileTu[offu + j] = lane; g_tileBu[offu + j] = j << 7; }
    if (lane == 31) g_ntilesu = pu;
}

// ---------------- phase A: dense MMA over exact tile list --------------------
// Per tile: cp.async-gather 128 pre-split rows + B tap image, 3-term bf16 MMA.
template <int CI>
__global__ __launch_bounds__(256)
void conv_mma_kernel(const char* __restrict__ xsp,     // rows of 4*CI bytes (hi|lo)
                     const char* __restrict__ btile,   // per tap 64 rows of 4*CI bytes
                     const int* __restrict__ ent,
                     const int* __restrict__ cnt,
                     const int* __restrict__ tileT,
                     const int* __restrict__ tileB,
                     const int* __restrict__ ntp,
                     float* __restrict__ msg, int n2)
{
    constexpr int AST  = CI + 8;          // padded row stride (bf16 elems)
    constexpr int RPB  = 4 * CI;          // gmem row pitch bytes (hi|lo)
    constexpr int CPR  = RPB / 16;        // 16B chunks per row
    constexpr int HALF = CPR / 2;
    constexpr uint32_t AlO  = 128u * AST * 2;
    constexpr uint32_t BhO  = 2u * 128u * AST * 2;
    constexpr uint32_t BlO  = BhO + 64u * AST * 2;
    constexpr uint32_t esmO = BlO + 64u * AST * 2;

    extern __shared__ char smem[];
    unsigned short* Ah = (unsigned short*)smem;
    unsigned short* Al = Ah + 128 * AST;
    unsigned short* Bh = Al + 128 * AST;
    unsigned short* Bl = Bh + 64 * AST;
    int* esm = (int*)(smem + esmO);
    const uint32_t sb = smem_u32(smem);

    const int tid = threadIdx.x, wid = tid >> 5, lane = tid & 31;
    const int gp = lane >> 2, tg = lane & 3;
    const int ntiles = *ntp;

    const int rowA = wid * 16 + gp;
    const unsigned short* ah0 = Ah + rowA * AST + tg * 2;
    const unsigned short* ah1 = ah0 + 8 * AST;
    const unsigned short* al0 = Al + rowA * AST + tg * 2;
    const unsigned short* al1 = al0 + 8 * AST;

    for (int idx = blockIdx.x; idx < ntiles; idx += gridDim.x) {
        const int t = tileT[idx], base = tileB[idx];
        const int nv = min(128, cnt[t] - base);
        __syncthreads();                 // smem free from previous tile
        if (tid < 128) esm[tid] = ent[(size_t)t * n2 + base + min(tid, nv - 1)];
        __syncthreads();

        // stage A (gathered rows, hi|lo)
        #pragma unroll
        for (int i = tid; i < 128 * CPR; i += 256) {
            int m = i / CPR, q = i - m * CPR;
            const char* src = xsp + (size_t)esm[m] * RPB + q * 16;
            int lo = (q >= HALF);
            int qq = q - lo * HALF;
            cp16(sb + (lo ? AlO : 0u) + m * (AST * 2) + qq * 16, src);
        }
        // stage B (contiguous tap image)
        #pragma unroll
        for (int i = tid; i < 64 * CPR; i += 256) {
            int o = i / CPR, q = i - o * CPR;
            const char* src = btile + (size_t)t * (64 * RPB) + (size_t)i * 16;
            int lo = (q >= HALF);
            int qq = q - lo * HALF;
            cp16(sb + (lo ? BlO : BhO) + o * (AST * 2) + qq * 16, src);
        }
        CP_COMMIT(); CP_WAIT0();
        __syncthreads();

        float acc[8][4];
        #pragma unroll
        for (int nt = 0; nt < 8; ++nt)
            #pragma unroll
            for (int j = 0; j < 4; ++j) acc[nt][j] = 0.f;

        #pragma unroll
        for (int s = 0; s < CI / 16; ++s) {
            const int kb = s * 16;
            uint32_t A0 = *(const uint32_t*)(ah0 + kb);
            uint32_t A1 = *(const uint32_t*)(ah1 + kb);
            uint32_t A2 = *(const uint32_t*)(ah0 + kb + 8);
            uint32_t A3 = *(const uint32_t*)(ah1 + kb + 8);
            uint32_t L0 = *(const uint32_t*)(al0 + kb);
            uint32_t L1 = *(const uint32_t*)(al1 + kb);
            uint32_t L2 = *(const uint32_t*)(al0 + kb + 8);
            uint32_t L3 = *(const uint32_t*)(al1 + kb + 8);
            #pragma unroll
            for (int nt = 0; nt < 8; ++nt) {
                const unsigned short* bh = Bh + (nt * 8 + gp) * AST + kb + tg * 2;
                const unsigned short* bl = Bl + (nt * 8 + gp) * AST + kb + tg * 2;
                uint32_t B0 = *(const uint32_t*)bh;
                uint32_t B1v = *(const uint32_t*)(bh + 8);
                uint32_t C0 = *(const uint32_t*)bl;
                uint32_t C1 = *(const uint32_t*)(bl + 8);
                mma16816(acc[nt][0], acc[nt][1], acc[nt][2], acc[nt][3],
                         A0, A1, A2, A3, B0, B1v);
                mma16816(acc[nt][0], acc[nt][1], acc[nt][2], acc[nt][3],
                         A0, A1, A2, A3, C0, C1);
                mma16816(acc[nt][0], acc[nt][1], acc[nt][2], acc[nt][3],
                         L0, L1, L2, L3, B0, B1v);
            }
        }

        // epilogue
        int m0 = wid * 16 + gp;
        int m1 = m0 + 8;
        float* d0 = msg + (size_t)(t * n2 + base + m0) * 64 + tg * 2;
        float* d1 = msg + (size_t)(t * n2 + base + m1) * 64 + tg * 2;
        bool v0 = (m0 < nv), v1 = (m1 < nv);
        #pragma unroll
        for (int nt = 0; nt < 8; ++nt) {
            if (v0) *(float2*)(d0 + nt * 8) = make_float2(acc[nt][0], acc[nt][1]);
            if (v1) *(float2*)(d1 + nt * 8) = make_float2(acc[nt][2], acc[nt][3]);
        }
    }
}

// ---------------- phase B: gather-sum + fused BN partials --------------------
__global__ __launch_bounds__(256)
void conv_sum_kernel(const float4* __restrict__ msg4, const int* __restrict__ pos,
                     float* __restrict__ pre, int n2)
{
    __shared__ float red[256 * 8];
    const int tid = threadIdx.x;
    const int base = blockIdx.x * 256;
    const int ro = tid >> 4, c4 = tid & 15;
    float s[4] = {0, 0, 0, 0}, s2[4] = {0, 0, 0, 0};
    for (int rr = ro; rr < 256; rr += 16) {
        int r = base + rr;
        if (r >= n2) break;
        float4 a = make_float4(0, 0, 0, 0);
        #pragma unroll 1
        for (int t = 0; t < 27; ++t) {
            int p = pos[t * n2 + r];
            if (p >= 0) {
                float4 m = msg4[(size_t)p * 16 + c4];
                a.x += m.x; a.y += m.y; a.z += m.z; a.w += m.w;
            }
        }
        ((float4*)pre)[(size_t)r * 16 + c4] = a;
        s[0] += a.x; s2[0] = fmaf(a.x, a.x, s2[0]);
        s[1] += a.y; s2[1] = fmaf(a.y, a.y, s2[1]);
        s[2] += a.z; s2[2] = fmaf(a.z, a.z, s2[2]);
        s[3] += a.w; s2[3] = fmaf(a.w, a.w, s2[3]);
    }
    #pragma unroll
    for (int j = 0; j < 4; ++j) { red[tid * 8 + j] = s[j]; red[tid * 8 + 4 + j] = s2[j]; }
    __syncthreads();
    if (tid < 64) {
        int cq = tid >> 2, jj = tid & 3;
        float ts = 0, t2 = 0;
        #pragma unroll
        for (int k = 0; k < 16; ++k) {
            ts += red[(k * 16 + cq) * 8 + jj];
            t2 += red[(k * 16 + cq) * 8 + 4 + jj];
        }
        g_part[(blockIdx.x * 64 + tid) * 2]     = ts;
        g_part[(blockIdx.x * 64 + tid) * 2 + 1] = t2;
    }
}

__global__ __launch_bounds__(256)
void up_sum_kernel(const float4* __restrict__ msg4, float* __restrict__ pre, int n2)
{
    __shared__ float red[256 * 8];
    const int tid = threadIdx.x;
    const int base = blockIdx.x * 256;
    const int ro = tid >> 4, c4 = tid & 15;
    float s[4] = {0, 0, 0, 0}, s2[4] = {0, 0, 0, 0};
    for (int rr = ro; rr < 256; rr += 16) {
        int r = base + rr;
        if (r >= n2) break;
        float4 a = msg4[(size_t)g_posup[r] * 16 + c4];
        ((float4*)pre)[(size_t)r * 16 + c4] = a;
        s[0] += a.x; s2[0] = fmaf(a.x, a.x, s2[0]);
        s[1] += a.y; s2[1] = fmaf(a.y, a.y, s2[1]);
        s[2] += a.z; s2[2] = fmaf(a.z, a.z, s2[2]);
        s[3] += a.w; s2[3] = fmaf(a.w, a.w, s2[3]);
    }
    #pragma unroll
    for (int j = 0; j < 4; ++j) { red[tid * 8 + j] = s[j]; red[tid * 8 + 4 + j] = s2[j]; }
    __syncthreads();
    if (tid < 64) {
        int cq = tid >> 2, jj = tid & 3;
        float ts = 0, t2 = 0;
        #pragma unroll
        for (int k = 0; k < 16; ++k) {
            ts += red[(k * 16 + cq) * 8 + jj];
            t2 += red[(k * 16 + cq) * 8 + 4 + jj];
        }
        g_part[(blockIdx.x * 64 + tid) * 2]     = ts;
        g_part[(blockIdx.x * 64 + tid) * 2 + 1] = t2;
    }
}

// ---------------- BN finalize + apply + ReLU ---------------------------------
// variant writing split bf16 planes (feeds next conv)
__global__ void bn_apply_split_kernel(const float* __restrict__ pre, int n,
                                      const float* __restrict__ gamma,
                                      const float* __restrict__ beta, int nparts,
                                      __nv_bfloat16* __restrict__ osp,
                                      int pitch, int looff)
{
    const int tid = threadIdx.x;
    const int c   = tid & 63;
    float s = 0.f, s2 = 0.f;
    for (int g = 0; g < nparts; ++g) {
        s  += g_part[(g * 64 + c) * 2];
        s2 += g_part[(g * 64 + c) * 2 + 1];
    }
    const float invn  = 1.f / (float)n;
    const float mean  = s * invn;
    const float var   = s2 * invn - mean * mean;
    const float inv   = rsqrtf(var + 1e-5f);
    const float scale = gamma[c] * inv;
    const float shift = beta[c] - mean * scale;
    const int rstep = gridDim.x * 4;
    for (int r = blockIdx.x * 4 + (tid >> 6); r < n; r += rstep) {
        float v = fmaxf(fmaf(pre[(size_t)r * 64 + c], scale, shift), 0.f);
        __nv_bfloat16 h = __float2bfloat16(v);
        osp[(size_t)r * pitch + c]         = h;
        osp[(size_t)r * pitch + looff + c] = __float2bfloat16(v - __bfloat162float(h));
    }
}

// final variant writing fp32 in place
__global__ void bn_apply_f32_kernel(float* __restrict__ buf, int n,
                                    const float* __restrict__ gamma,
                                    const float* __restrict__ beta, int nparts)
{
    const int tid = threadIdx.x;
    const int c   = tid & 63;
    float s = 0.f, s2 = 0.f;
    for (int g = 0; g < nparts; ++g) {
        s  += g_part[(g * 64 + c) * 2];
        s2 += g_part[(g * 64 + c) * 2 + 1];
    }
    const float invn  = 1.f / (float)n;
    const float mean  = s * invn;
    const float var   = s2 * invn - mean * mean;
    const float inv   = rsqrtf(var + 1e-5f);
    const float scale = gamma[c] * inv;
    const float shift = beta[c] - mean * scale;
    const int rstep = gridDim.x * 4;
    for (int r = blockIdx.x * 4 + (tid >> 6); r < n; r += rstep) {
        float v = fmaf(buf[(size_t)r * 64 + c], scale, shift);
        buf[(size_t)r * 64 + c] = fmaxf(v, 0.f);
    }
}

// ---------------- launch ------------------------------------------------------
extern "C" void kernel_launch(void* const* d_in, const int* in_sizes, int n_in,
                              void* d_out, int out_size)
{
    const float* feats1   = (const float*)d_in[0];
    const float* feats2   = (const float*)d_in[1];
    const float* w_up     = (const float*)d_in[2];
    const float* gamma_up = (const float*)d_in[3];
    const float* beta_up  = (const float*)d_in[4];
    const float* w1       = (const float*)d_in[5];
    const float* gamma1   = (const float*)d_in[6];
    const float* beta1    = (const float*)d_in[7];
    const float* w2       = (const float*)d_in[8];
    const float* gamma2   = (const float*)d_in[9];
    const float* beta2    = (const float*)d_in[10];
    const int*   up_src   = (const int*)d_in[11];
    const int*   up_kidx  = (const int*)d_in[12];
    const int*   nbr_src  = (const int*)d_in[13];
    float*       out      = (float*)d_out;

    const int n1 = in_sizes[0] / 128;
    const int n2 = in_sizes[1] / 64;

    char *f1sp, *xsp, *hsp, *Bup, *B1, *B2;
    float *pre, *msg;
    int *ent, *entup, *cnt, *cntup, *pos;
    int *tileT, *tileB, *tileTu, *tileBu, *ntp, *ntpu;
    __nv_bfloat16 *xsp_b, *hsp_b;
    cudaGetSymbolAddress((void**)&f1sp,  g_f1sp);
    cudaGetSymbolAddress((void**)&xsp,   g_xsp);
    cudaGetSymbolAddress((void**)&hsp,   g_hsp);
    cudaGetSymbolAddress((void**)&pre,   g_pre);
    cudaGetSymbolAddress((void**)&msg,   g_msg);
    cudaGetSymbolAddress((void**)&ent,   g_ent);
    cudaGetSymbolAddress((void**)&entup, g_entup);
    cudaGetSymbolAddress((void**)&cnt,   g_cnt);
    cudaGetSymbolAddress((void**)&cntup, g_cntup);
    cudaGetSymbolAddress((void**)&pos,   g_pos);
    cudaGetSymbolAddress((void**)&Bup,   g_Bup);
    cudaGetSymbolAddress((void**)&B1,    g_B1);
    cudaGetSymbolAddress((void**)&B2,    g_B2);
    cudaGetSymbolAddress((void**)&tileT, g_tileT);
    cudaGetSymbolAddress((void**)&tileB, g_tileB);
    cudaGetSymbolAddress((void**)&tileTu, g_tileTu);
    cudaGetSymbolAddress((void**)&tileBu, g_tileBu);
    cudaGetSymbolAddress((void**)&ntp,   g_ntiles);
    cudaGetSymbolAddress((void**)&ntpu,  g_ntilesu);
    xsp_b = (__nv_bfloat16*)xsp;
    hsp_b = (__nv_bfloat16*)hsp;

    // smem: 2*128*(CI+8)*2 + 2*64*(CI+8)*2 + 512
    const int SM128 = 2 * 128 * 136 * 2 + 2 * 64 * 136 * 2 + 512;  // 104960
    const int SM64  = 2 * 128 * 72  * 2 + 2 * 64 * 72  * 2 + 512;  // 55808
    cudaFuncSetAttribute(conv_mma_kernel<128>,
                         cudaFuncAttributeMaxDynamicSharedMemorySize, SM128);
    cudaFuncSetAttribute(conv_mma_kernel<64>,
                         cudaFuncAttributeMaxDynamicSharedMemorySize, SM64);

    const int nbSum = (n2 + 255) / 256;      // 235 <= 256 partial slots
    const int nbApply = 256;
    const int NBMMA = 1024;

    // 0: prep (counters, input/weight splits)
    prep_kernel<<<2048, 256>>>(feats1, feats2, w_up, w1, w2, n1, n2);
    // 1: compaction fills + exact tile lists
    fill_up_kernel<<<(n2 + 255) / 256, 256>>>(up_src, up_kidx, n2);
    fill_nbr_kernel<<<(27 * n2 + 255) / 256, 256>>>(nbr_src, n2);
    build_tiles_kernel<<<1, 32>>>();

    // upsample
    conv_mma_kernel<128><<<NBMMA, 256, SM128>>>(f1sp, Bup, entup, cntup,
                                                tileTu, tileBu, ntpu, msg, n2);
    up_sum_kernel<<<nbSum, 256>>>((const float4*)msg, pre, n2);
    bn_apply_split_kernel<<<nbApply, 256>>>(pre, n2, gamma_up, beta_up, nbSum,
                                            xsp_b, 256, 128);

    // conv1
    conv_mma_kernel<128><<<NBMMA, 256, SM128>>>(xsp, B1, ent, cnt,
                                                tileT, tileB, ntp, msg, n2);
    conv_sum_kernel<<<nbSum, 256>>>((const float4*)msg, pos, pre, n2);
    bn_apply_split_kernel<<<nbApply, 256>>>(pre, n2, gamma1, beta1, nbSum,
                                            hsp_b, 128, 64);

    // conv2
    conv_mma_kernel<64><<<NBMMA, 256, SM64>>>(hsp, B2, ent, cnt,
                                              tileT, tileB, ntp, msg, n2);
    conv_sum_kernel<<<nbSum, 256>>>((const float4*)msg, pos, out, n2);
    bn_apply_f32_kernel<<<nbApply, 256>>>(out, n2, gamma2, beta2, nbSum);
}